// round 1
// baseline (speedup 1.0000x reference)
#include <cuda_runtime.h>
#include <math.h>

#define BSZ 256
#define IND 64
#define HID 128
#define NB 50
#define S1 51
#define ROWS_PER_B (S1 * S1)                                   // 2601
#define TILE_ROWS 64
#define TILES_PER_B ((ROWS_PER_B + TILE_ROWS - 1) / TILE_ROWS) // 41
#define NTILES (BSZ * TILES_PER_B)                             // 10496
#define PI_D 3.14159265358979323846

// -------- scratch (device globals; no allocations allowed) --------
__device__ float g_steps[S1];
__device__ float g_cc[S1];
__device__ float g_xmax;
__device__ float g_base[BSZ * HID];   // h @ iw0[1:,:] + ib0
__device__ float g_off[BSZ];          // o[:,0]
__device__ float g_lsc[BSZ];          // o[:,1] (pre-exp)
__device__ float g_part[NTILES];      // per-tile partial of the double quadrature

// ================= kernel 1: constants + xmax =================
__global__ void prep_kernel(const float* __restrict__ x) {
    __shared__ float st_s[S1];
    __shared__ float red[256];
    int tx = threadIdx.x;
    if (tx < S1) {
        double st = cos((double)tx * PI_D / (double)NB);
        st_s[tx] = (float)st;
        g_steps[tx] = (float)st;
        // cc[tx] = sum_i lam[i][tx] * W[i]  (all in double, like numpy)
        double sum = 0.0;
        for (int i = 0; i <= NB; i++) {
            double lam;
            if (tx == 0) lam = 0.5;
            else {
                lam = cos((double)i * (double)tx * PI_D / (double)NB);
                if (tx == NB) lam *= 0.5;
            }
            lam *= 2.0 / (double)NB;
            double W;
            if (i == 0) W = 1.0;
            else if (i & 1) W = 0.0;
            else W = 2.0 / (1.0 - (double)i * (double)i);
            sum += lam * W;
        }
        g_cc[tx] = (float)sum;
    }
    __syncthreads();
    float mx = -3.0e38f;
    if (tx < BSZ) {
        float xb = x[tx];
        for (int i = 0; i < S1; i++) {
            float t = (xb * (st_s[i] + 1.0f)) * 0.5f;
            mx = fmaxf(mx, t);
        }
    }
    red[tx] = mx;
    __syncthreads();
    for (int off = 128; off > 0; off >>= 1) {
        if (tx < off) red[tx] = fmaxf(red[tx], red[tx + off]);
        __syncthreads();
    }
    if (tx == 0) g_xmax = red[0] + 10.0f;
}

// ================= kernel 2: base[b,k] = ib0[k] + h[b,:] @ iw0[1:,:] =================
__global__ void base_kernel(const float* __restrict__ h,
                            const float* __restrict__ iw0,
                            const float* __restrict__ ib0) {
    __shared__ float h_s[IND - 1];
    int b = blockIdx.x, k = threadIdx.x;
    if (k < IND - 1) h_s[k] = h[b * (IND - 1) + k];
    __syncthreads();
    float acc = ib0[k];
    for (int d = 0; d < IND - 1; d++)
        acc = fmaf(h_s[d], iw0[(d + 1) * HID + k], acc);
    g_base[b * HID + k] = acc;
}

// ================= kernel 3: offset / scaling MLP =================
__global__ void nmlp_kernel(const float* __restrict__ h,
                            const float* __restrict__ nw0, const float* __restrict__ nb0,
                            const float* __restrict__ nw1, const float* __restrict__ nb1,
                            const float* __restrict__ nw2, const float* __restrict__ nb2) {
    __shared__ float h_s[IND - 1];
    __shared__ float a_s[HID];
    __shared__ float a2_s[HID];
    int b = blockIdx.x, k = threadIdx.x;
    if (k < IND - 1) h_s[k] = h[b * (IND - 1) + k];
    __syncthreads();
    float acc = nb0[k];
    for (int d = 0; d < IND - 1; d++)
        acc = fmaf(h_s[d], nw0[d * HID + k], acc);
    a_s[k] = fmaxf(acc, 0.0f);
    __syncthreads();
    acc = nb1[k];
    for (int m = 0; m < HID; m++)
        acc = fmaf(a_s[m], nw1[m * HID + k], acc);
    a2_s[k] = fmaxf(acc, 0.0f);
    __syncthreads();
    if (k < 2) {
        float o = nb2[k];
        for (int n = 0; n < HID; n++)
            o = fmaf(a2_s[n], nw2[n * 2 + k], o);
        if (k == 0) g_off[b] = o; else g_lsc[b] = o;
    }
}

// ================= kernel 4: main fused GEMM =================
// Per tile: 64 rows (flattened (i,j) grid for one b) x 128 hidden.
// a0 generated in-smem (rank-1 layer 1), GEMM against smem-resident iw1,
// fused relu -> iw2 dot -> elu+1 -> CC-weighted reduction epilogue.
#define SMEM_FLOATS (16384 + 8192 + 128 + 128 + 128 + 128 + 64 + 64 + 64 + 64 + 8)

__global__ void __launch_bounds__(256, 2)
main_kernel(const float* __restrict__ x,
            const float* __restrict__ iw0,
            const float* __restrict__ iw1,
            const float* __restrict__ ib1,
            const float* __restrict__ iw2,
            const float* __restrict__ ib2) {
    extern __shared__ float sm[];
    float* w1_s    = sm;                 // [128][128]
    float* a0_t    = sm + 16384;         // [m=128][row=64] (transposed)
    float* base_s  = a0_t + 8192;        // 128
    float* w0s_s   = base_s + 128;       // 128 (iw0 row 0)
    float* ib1_s   = w0s_s + 128;        // 128
    float* iw2_s   = ib1_s + 128;        // 128
    float* steps_s = iw2_s + 128;        // 64
    float* cc_s    = steps_s + 64;       // 64
    float* s_s     = cc_s + 64;          // 64
    float* wr_s    = s_s + 64;           // 64 (per-row quadrature weight)
    float* red_s   = wr_s + 64;          // 8

    const int tx = threadIdx.x;
    const int warp = tx >> 5, lane = tx & 31;
    const int r0 = warp * 8;             // 8 rows per thread
    const int k0 = lane * 4;             // 4 cols per thread

    for (int idx = tx; idx < HID * HID; idx += 256) w1_s[idx] = iw1[idx];
    if (tx < HID) {
        w0s_s[tx] = iw0[tx];
        ib1_s[tx] = ib1[tx];
        iw2_s[tx] = iw2[tx];
    }
    if (tx < S1) { steps_s[tx] = g_steps[tx]; cc_s[tx] = g_cc[tx]; }
    const float xmax = g_xmax;
    const float ib2v = ib2[0];
    __syncthreads();

    int prev_b = -1;
    for (int tile = blockIdx.x; tile < NTILES; tile += gridDim.x) {
        const int b = tile / TILES_PER_B;
        const int trow0 = (tile - b * TILES_PER_B) * TILE_ROWS;

        __syncthreads();   // protect smem from previous iteration's readers
        if (b != prev_b) {
            if (tx < HID) base_s[tx] = g_base[b * HID + tx];
            prev_b = b;
        }
        if (tx < TILE_ROWS) {
            int r = trow0 + tx;
            float s = 0.0f, w = 0.0f;
            if (r < ROWS_PER_B) {
                int i = r / S1, j = r - i * S1;
                float xb = x[b];
                float tbi = (xb * (steps_s[i] + 1.0f)) * 0.5f;
                float rem = xmax - tbi;
                s = tbi + (rem * (steps_s[j] + 1.0f)) * 0.5f;
                w = cc_s[i] * cc_s[j] * rem * 0.5f;   // x[b]/2 applied at the end
            }
            s_s[tx] = s;
            wr_s[tx] = w;
        }
        __syncthreads();

        // layer 1 (rank-1): a0_t[m][row] = relu(s*w0s[m] + base[m])
        for (int idx = tx; idx < HID * TILE_ROWS; idx += 256) {
            int m = idx >> 6, row = idx & 63;
            a0_t[idx] = fmaxf(fmaf(s_s[row], w0s_s[m], base_s[m]), 0.0f);
        }
        __syncthreads();

        // layer 2 GEMM: acc[r][c] = sum_m a0[row][m] * iw1[m][k]
        float acc[8][4];
        #pragma unroll
        for (int r = 0; r < 8; r++)
            #pragma unroll
            for (int c = 0; c < 4; c++) acc[r][c] = 0.0f;

        #pragma unroll 8
        for (int m = 0; m < HID; m++) {
            float4 wv  = *(const float4*)&w1_s[m * HID + k0];
            float4 a0v = *(const float4*)&a0_t[m * TILE_ROWS + r0];
            float4 a1v = *(const float4*)&a0_t[m * TILE_ROWS + r0 + 4];
            float av[8] = {a0v.x, a0v.y, a0v.z, a0v.w, a1v.x, a1v.y, a1v.z, a1v.w};
            #pragma unroll
            for (int r = 0; r < 8; r++) {
                acc[r][0] = fmaf(av[r], wv.x, acc[r][0]);
                acc[r][1] = fmaf(av[r], wv.y, acc[r][1]);
                acc[r][2] = fmaf(av[r], wv.z, acc[r][2]);
                acc[r][3] = fmaf(av[r], wv.w, acc[r][3]);
            }
        }

        // epilogue: relu(+ib1) -> dot iw2 -> elu+1 -> weighted accumulate
        float part = 0.0f;
        #pragma unroll
        for (int r = 0; r < 8; r++) {
            float pr = fmaxf(acc[r][0] + ib1_s[k0 + 0], 0.0f) * iw2_s[k0 + 0]
                     + fmaxf(acc[r][1] + ib1_s[k0 + 1], 0.0f) * iw2_s[k0 + 1]
                     + fmaxf(acc[r][2] + ib1_s[k0 + 2], 0.0f) * iw2_s[k0 + 2]
                     + fmaxf(acc[r][3] + ib1_s[k0 + 3], 0.0f) * iw2_s[k0 + 3];
            #pragma unroll
            for (int off = 16; off > 0; off >>= 1)
                pr += __shfl_xor_sync(0xffffffffu, pr, off);
            if (lane == 0) {
                float z = pr + ib2v;
                float f = (z > 0.0f) ? (z + 1.0f) : expf(z);   // elu(z)+1
                part = fmaf(f, wr_s[r0 + r], part);
            }
        }
        if (lane == 0) red_s[warp] = part;
        __syncthreads();
        if (tx == 0) {
            float sum = 0.0f;
            #pragma unroll
            for (int wi = 0; wi < 8; wi++) sum += red_s[wi];
            g_part[tile] = sum;
        }
    }
}

// ================= kernel 5: final combine =================
__global__ void final_kernel(const float* __restrict__ x, float* __restrict__ out) {
    int b = threadIdx.x;
    if (b < BSZ) {
        float sum = 0.0f;
        for (int k = 0; k < TILES_PER_B; k++) sum += g_part[b * TILES_PER_B + k];
        float outer = (sum * x[b]) * 0.5f;
        out[b] = expf(g_lsc[b]) * outer + g_off[b];
    }
}

// ================= launch =================
extern "C" void kernel_launch(void* const* d_in, const int* in_sizes, int n_in,
                              void* d_out, int out_size) {
    const float* x   = (const float*)d_in[0];
    const float* h   = (const float*)d_in[1];
    const float* iw0 = (const float*)d_in[2];
    const float* ib0 = (const float*)d_in[3];
    const float* iw1 = (const float*)d_in[4];
    const float* ib1 = (const float*)d_in[5];
    const float* iw2 = (const float*)d_in[6];
    const float* ib2 = (const float*)d_in[7];
    const float* nw0 = (const float*)d_in[8];
    const float* nb0 = (const float*)d_in[9];
    const float* nw1 = (const float*)d_in[10];
    const float* nb1 = (const float*)d_in[11];
    const float* nw2 = (const float*)d_in[12];
    const float* nb2 = (const float*)d_in[13];
    float* out = (float*)d_out;
    (void)in_sizes; (void)n_in; (void)out_size;

    const int smem_bytes = SMEM_FLOATS * (int)sizeof(float);   // ~99 KB
    cudaFuncSetAttribute(main_kernel,
                         cudaFuncAttributeMaxDynamicSharedMemorySize, smem_bytes);

    prep_kernel<<<1, 256>>>(x);
    base_kernel<<<BSZ, HID>>>(h, iw0, ib0);
    nmlp_kernel<<<BSZ, HID>>>(h, nw0, nb0, nw1, nb1, nw2, nb2);
    main_kernel<<<296, 256, smem_bytes>>>(x, iw0, iw1, ib1, iw2, ib2);
    final_kernel<<<1, 256>>>(x, out);
}

// round 2
// speedup vs baseline: 4.1612x; 4.1612x over previous
#include <cuda_runtime.h>
#include <math.h>

#define BSZ 256
#define IND 64
#define HID 128
#define NB 50
#define S1 51
#define ROWS (S1 * S1)          // 2601
#define ST 132                  // padded segment stride (floats), 16B-aligned, odd/4
#define SEGF (129 * ST)         // 17028 floats per segment array
#define PI_D 3.14159265358979323846

// smem float layout offsets
#define OFF_B     (2 * SEGF)          // base_s 128
#define OFF_W0    (OFF_B + 128)       // w0_s 128
#define OFF_BP    (OFF_W0 + 128)      // bp_s 128
#define OFF_STEPS (OFF_BP + 128)      // 64
#define OFF_CC    (OFF_STEPS + 64)    // 64
#define OFF_RED   (OFF_CC + 64)       // 256
#define OFF_O     (OFF_RED + 256)     // 4
#define OFF_MI    (OFF_O + 4)         // 128 (int)
#define OFF_H     (OFF_MI + 128)      // 64
#define SMEM_FLOATS (OFF_H + 64)      // 35080 floats = 140320 B

__device__ float g_steps[S1];
__device__ float g_cc[S1];
__device__ float g_xmax;
__device__ int   g_iperm[HID];   // logical hidden k -> physical slot
__device__ int   g_npos;         // #k with iw2 >= 0

// ===================== prep: CC weights, xmax, sign permutation =====================
__global__ void prep_kernel(const float* __restrict__ x, const float* __restrict__ iw2) {
    __shared__ float st_s[S1];
    __shared__ double part[256];
    __shared__ float red[256];
    int tx = threadIdx.x;
    if (tx < S1) {
        double st = cos((double)tx * PI_D / (double)NB);
        st_s[tx] = (float)st;
        g_steps[tx] = (float)st;
    }
    // cc[c] = sum over even i of lam(i,c)*W(i); deterministic partial layout
    double p = 0.0;
    if (tx < 255) {
        int c = tx / 5, u = tx % 5;
        for (int ie = u; ie < 26; ie += 5) {
            int i = 2 * ie;
            double W = (i == 0) ? 1.0 : 2.0 / (1.0 - (double)i * (double)i);
            double l;
            if (c == 0) l = 0.5;
            else {
                l = cos((double)i * (double)c * PI_D / (double)NB);
                if (c == NB) l *= 0.5;
            }
            p += l * (2.0 / (double)NB) * W;
        }
    }
    part[tx] = p;
    __syncthreads();
    if (tx < S1) {
        double s = 0.0;
        for (int u = 0; u < 5; u++) s += part[tx * 5 + u];
        g_cc[tx] = (float)s;
    }
    // xmax = max over (b,i) of x_b*(step_i+1)/2, plus 10
    float mx = -3.0e38f;
    if (tx < BSZ) {
        float xb = x[tx];
        for (int i = 0; i < S1; i++)
            mx = fmaxf(mx, xb * (st_s[i] + 1.0f) * 0.5f);
    }
    red[tx] = mx;
    __syncthreads();
    for (int o = 128; o > 0; o >>= 1) {
        if (tx < o) red[tx] = fmaxf(red[tx], red[tx + o]);
        __syncthreads();
    }
    if (tx == 0) {
        g_xmax = red[0] + 10.0f;
        int P = 0;
        for (int k = 0; k < HID; k++) if (iw2[k] >= 0.0f) g_iperm[k] = P++;
        g_npos = P;
        for (int k = 0; k < HID; k++) if (iw2[k] < 0.0f)  g_iperm[k] = P++;
    }
}

// ===================== main: one block per batch element =====================
__global__ void __launch_bounds__(256, 1)
main_kernel(const float* __restrict__ x,   const float* __restrict__ h,
            const float* __restrict__ iw0, const float* __restrict__ ib0,
            const float* __restrict__ iw1, const float* __restrict__ ib1,
            const float* __restrict__ iw2, const float* __restrict__ ib2,
            const float* __restrict__ nw0, const float* __restrict__ nb0,
            const float* __restrict__ nw1, const float* __restrict__ nb1,
            const float* __restrict__ nw2, const float* __restrict__ nb2,
            float* __restrict__ out)
{
    extern __shared__ float sm[];
    float* Aseg    = sm;
    float* Bseg    = sm + SEGF;
    float* base_s  = sm + OFF_B;
    float* w0_s    = sm + OFF_W0;
    float* bp_s    = sm + OFF_BP;
    float* steps_s = sm + OFF_STEPS;
    float* cc_s    = sm + OFF_CC;
    float* red_s   = sm + OFF_RED;
    float* o_s     = sm + OFF_O;
    int*   mi_s    = (int*)(sm + OFF_MI);
    float* h_s     = sm + OFF_H;

    const int tx = threadIdx.x;
    const int b  = blockIdx.x;
    const float xb    = x[b];
    const float xmax  = g_xmax;
    const float ib2v  = ib2[0];
    const int   npos  = g_npos;

    if (tx < IND - 1) h_s[tx] = h[b * (IND - 1) + tx];
    if (tx < S1) { steps_s[tx] = g_steps[tx]; cc_s[tx] = g_cc[tx]; }
    __syncthreads();

    // ---- base_b[m], w0[m], breakpoints ----
    if (tx < HID) {
        float acc = ib0[tx];
        #pragma unroll 7
        for (int d = 0; d < IND - 1; ++d)
            acc = fmaf(h_s[d], iw0[(d + 1) * HID + tx], acc);
        base_s[tx] = acc;
        float w0m = iw0[tx];
        w0_s[tx] = w0m;
        float ss;
        if (w0m != 0.0f) ss = -acc / w0m;
        else ss = (acc > 0.0f) ? __int_as_float(0x7f800000) : __int_as_float(0xff800000);
        bp_s[tx] = ss;
        mi_s[tx] = tx;
    }
    // ---- nmlp (offset/scaling head), scratch in Aseg ----
    float* a_s  = Aseg;
    float* a2_s = Aseg + 128;
    if (tx < HID) {
        float acc = nb0[tx];
        #pragma unroll 7
        for (int d = 0; d < IND - 1; ++d)
            acc = fmaf(h_s[d], nw0[d * HID + tx], acc);
        a_s[tx] = fmaxf(acc, 0.0f);
    }
    __syncthreads();
    if (tx < HID) {
        float acc = nb1[tx];
        #pragma unroll 8
        for (int m = 0; m < HID; ++m)
            acc = fmaf(a_s[m], nw1[m * HID + tx], acc);
        a2_s[tx] = fmaxf(acc, 0.0f);
    }
    __syncthreads();
    {   // layer 2: two outputs, deterministic warp reductions
        int o  = tx >> 7;          // 0: offset, 1: log-scale
        int n2 = tx & 127;
        float p = a2_s[n2] * nw2[n2 * 2 + o];
        #pragma unroll
        for (int off = 16; off >= 1; off >>= 1)
            p += __shfl_xor_sync(0xffffffffu, p, off);
        if ((tx & 31) == 0) red_s[tx >> 5] = p;
        __syncthreads();
        if (tx == 0)   o_s[0] = nb2[0] + ((red_s[0] + red_s[1]) + (red_s[2] + red_s[3]));
        if (tx == 128) o_s[1] = nb2[1] + ((red_s[4] + red_s[5]) + (red_s[6] + red_s[7]));
    }
    __syncthreads();

    // ---- bitonic sort of 128 breakpoints (ascending) with payload ----
    for (int kk = 2; kk <= 128; kk <<= 1) {
        for (int j = kk >> 1; j > 0; j >>= 1) {
            if (tx < 128) {
                int ixj = tx ^ j;
                if (ixj > tx) {
                    float a = bp_s[tx], c = bp_s[ixj];
                    bool up = ((tx & kk) == 0);
                    if ((a > c) == up) {
                        bp_s[tx] = c; bp_s[ixj] = a;
                        int t2 = mi_s[tx]; mi_s[tx] = mi_s[ixj]; mi_s[ixj] = t2;
                    }
                }
            }
            __syncthreads();
        }
    }

    // ---- build segment prefix vectors A_g, B_g (iw2, ib1 folded in) ----
    {
        int k = tx & 127;                    // logical hidden column
        bool isA = (tx < 128);
        int kp = g_iperm[k];                 // physical slot (sign-grouped)
        float w2k = iw2[k];
        float* seg = isA ? Aseg : Bseg;
        float r = isA ? 0.0f : ib1[k] * w2k;
        // backward pass: type- (w0m <= 0) active for segments g <= pos
        #pragma unroll 4
        for (int g = 128; g >= 1; --g) {
            seg[g * ST + kp] = r;
            int m = mi_s[g - 1];
            float w0m = w0_s[m];
            float wv = iw1[m * HID + k] * w2k;
            float coef = isA ? w0m : base_s[m];
            coef = (w0m <= 0.0f) ? coef : 0.0f;
            r = fmaf(coef, wv, r);
        }
        seg[kp] = r;
        // forward pass: type+ (w0m > 0) active for segments g > pos
        r = 0.0f;
        #pragma unroll 4
        for (int g = 0; g < 128; ++g) {
            int m = mi_s[g];
            float w0m = w0_s[m];
            float wv = iw1[m * HID + k] * w2k;
            float coef = isA ? w0m : base_s[m];
            coef = (w0m > 0.0f) ? coef : 0.0f;
            r = fmaf(coef, wv, r);
            seg[(g + 1) * ST + kp] += r;
        }
    }
    __syncthreads();

    // ---- quadrature row loop: 2601 points ----
    float total = 0.0f;
    const int kpos4 = npos & ~3;
    for (int rb = 0; rb < ROWS; rb += 256) {
        int r = rb + tx;
        if (r < ROWS) {
            int i = r / S1, j = r - i * S1;
            float tbi = xb * (steps_s[i] + 1.0f) * 0.5f;
            float rem = xmax - tbi;
            float s = fmaf(rem, (steps_s[j] + 1.0f) * 0.5f, tbi);
            float wt = cc_s[i] * cc_s[j] * rem * 0.5f;
            // binary search: g = #breakpoints < s
            int g = 0;
            #pragma unroll
            for (int stp = 64; stp >= 1; stp >>= 1) {
                int cand = g + stp;
                if (cand <= 128 && bp_s[cand - 1] < s) g = cand;
            }
            const float* Ag = Aseg + g * ST;
            const float* Bg = Bseg + g * ST;
            float pr = 0.0f;
            int k = 0;
            #pragma unroll 4
            for (; k < kpos4; k += 4) {
                float4 a4 = *(const float4*)(Ag + k);
                float4 b4 = *(const float4*)(Bg + k);
                pr += fmaxf(fmaf(s, a4.x, b4.x), 0.0f);
                pr += fmaxf(fmaf(s, a4.y, b4.y), 0.0f);
                pr += fmaxf(fmaf(s, a4.z, b4.z), 0.0f);
                pr += fmaxf(fmaf(s, a4.w, b4.w), 0.0f);
            }
            for (; k < npos; ++k)
                pr += fmaxf(fmaf(s, Ag[k], Bg[k]), 0.0f);
            for (; k & 3; ++k)
                pr += fminf(fmaf(s, Ag[k], Bg[k]), 0.0f);
            #pragma unroll 4
            for (; k < HID; k += 4) {
                float4 a4 = *(const float4*)(Ag + k);
                float4 b4 = *(const float4*)(Bg + k);
                pr += fminf(fmaf(s, a4.x, b4.x), 0.0f);
                pr += fminf(fmaf(s, a4.y, b4.y), 0.0f);
                pr += fminf(fmaf(s, a4.z, b4.z), 0.0f);
                pr += fminf(fmaf(s, a4.w, b4.w), 0.0f);
            }
            float z = pr + ib2v;
            float f = (z > 0.0f) ? (z + 1.0f) : expf(z);   // elu(z)+1
            total = fmaf(f, wt, total);
        }
    }

    // ---- deterministic block reduction + final combine ----
    red_s[tx] = total;
    __syncthreads();
    for (int o = 128; o > 0; o >>= 1) {
        if (tx < o) red_s[tx] += red_s[tx + o];
        __syncthreads();
    }
    if (tx == 0) {
        float outer = red_s[0] * xb * 0.5f;
        out[b] = expf(o_s[1]) * outer + o_s[0];
    }
}

// ===================== launch =====================
extern "C" void kernel_launch(void* const* d_in, const int* in_sizes, int n_in,
                              void* d_out, int out_size) {
    const float* x   = (const float*)d_in[0];
    const float* h   = (const float*)d_in[1];
    const float* iw0 = (const float*)d_in[2];
    const float* ib0 = (const float*)d_in[3];
    const float* iw1 = (const float*)d_in[4];
    const float* ib1 = (const float*)d_in[5];
    const float* iw2 = (const float*)d_in[6];
    const float* ib2 = (const float*)d_in[7];
    const float* nw0 = (const float*)d_in[8];
    const float* nb0 = (const float*)d_in[9];
    const float* nw1 = (const float*)d_in[10];
    const float* nb1 = (const float*)d_in[11];
    const float* nw2 = (const float*)d_in[12];
    const float* nb2 = (const float*)d_in[13];
    float* out = (float*)d_out;
    (void)in_sizes; (void)n_in; (void)out_size;

    const int smem_bytes = SMEM_FLOATS * (int)sizeof(float);
    cudaFuncSetAttribute(main_kernel,
                         cudaFuncAttributeMaxDynamicSharedMemorySize, smem_bytes);

    prep_kernel<<<1, 256>>>(x, iw2);
    main_kernel<<<BSZ, 256, smem_bytes>>>(x, h, iw0, ib0, iw1, ib1, iw2, ib2,
                                          nw0, nb0, nw1, nb1, nw2, nb2, out);
}